// round 6
// baseline (speedup 1.0000x reference)
#include <cuda_runtime.h>
#include <cuda_bf16.h>
#include <cstdint>

// Problem constants
#define N_TOK   262144
#define DIM     384
#define KCODES  512
#define BETA    0.25f

// Tiling
#define TM      64      // tokens per block
#define TK      128     // codes per chunk
#define DKC     32      // D chunk
#define NBLOCKS (N_TOK / TM)   // 4096
#define TAU     1e-3f   // candidate margin
#define MAXCAND 16

__device__ float g_esq[KCODES];   // XLA-emulated e_sq
__device__ float g_part[NBLOCKS];

// ---- packed f32x2 helpers (sm_100+) ----
#define FMA_F32X2(d, a, b, c) \
    asm("fma.rn.f32x2 %0, %1, %2, %3;" : "=l"(d) : "l"(a), "l"(b), "l"(c))

__device__ __forceinline__ unsigned long long pack2(float v) {
    unsigned long long r;
    unsigned int b = __float_as_uint(v);
    asm("mov.b64 %0, {%1, %1};" : "=l"(r) : "r"(b));
    return r;
}
__device__ __forceinline__ void unpack2(float& lo, float& hi, unsigned long long p) {
    unsigned int a, b;
    asm("mov.b64 {%0, %1}, %2;" : "=r"(a), "=r"(b) : "l"(p));
    lo = __uint_as_float(a);
    hi = __uint_as_float(b);
}

// ============================================================
// XLA:GPU row-reduction emulation for sum(x*x), row length 384.
// Config: num_threads_x = 192, vector_size = 2 (one pass).
//   lane pair-sum:  P_t = fl( fl(x[2t]*x[2t]) + fl(x[2t+1]*x[2t+1]) )
//   per-warp shfl_down tree (16,8,4,2,1) over 32 pair-sums -> W_w (6 warps)
//   cross-warp (warp0 tree over lanes 0..5, zero-padded, exact no-ops):
//     Z = ((W0+W4)+W2) + ((W1+W5)+W3)
// ============================================================
__device__ float xla_rowsum_sq_192(const float* __restrict__ x) {
    float W[6];
    #pragma unroll
    for (int w = 0; w < 6; w++) {
        float P[32];
        #pragma unroll
        for (int t = 0; t < 32; t++) {
            int b = (w * 32 + t) * 2;
            float p0 = __fmul_rn(x[b], x[b]);
            float p1 = __fmul_rn(x[b + 1], x[b + 1]);
            P[t] = __fadd_rn(p0, p1);
        }
        #pragma unroll
        for (int off = 16; off >= 1; off >>= 1) {
            #pragma unroll
            for (int t = 0; t < 16; t++) {
                if (t < off) P[t] = __fadd_rn(P[t], P[t + off]);
            }
        }
        W[w] = P[0];
    }
    float l0 = __fadd_rn(__fadd_rn(W[0], W[4]), W[2]);
    float l1 = __fadd_rn(__fadd_rn(W[1], W[5]), W[3]);
    return __fadd_rn(l0, l1);
}

// Reference-pipeline score:
//   M32 = sequential fp32 FMA chain, k ascending (cuBLAS sgemm accumulator)
//   v1  = fl32(Z32 - 2*M32)   (*2 exact, one rounding)
//   v2  = fl32(v1 + esq32)
__device__ __forceinline__ float exact_score(const float* __restrict__ zr,
                                             const float* __restrict__ er,
                                             float Z32, float esq32) {
    float acc = 0.f;
    #pragma unroll 4
    for (int d = 0; d < DIM; d++)
        acc = __fmaf_rn(zr[d], er[d], acc);
    float v1 = __fadd_rn(Z32, __fmul_rn(-2.f, acc));
    return __fadd_rn(v1, esq32);
}

// ============================================================
// Kernel 1: e_sq[k] with XLA row-reduce emulation
// ============================================================
__global__ void vq_esq_kernel(const float* __restrict__ emb) {
    int k = blockIdx.x * blockDim.x + threadIdx.x;
    if (k < KCODES)
        g_esq[k] = xla_rowsum_sq_192(emb + (size_t)k * DIM);
}

// ============================================================
// Kernel 2: main — fast scores, candidate collection, exact refine,
//           gather, per-block loss partial
// ============================================================
__global__ __launch_bounds__(256)
void vq_main_kernel(const float* __restrict__ z,
                    const float* __restrict__ emb,
                    float* __restrict__ out) {
    __shared__ float sz[DKC][TM];     // z tile, transposed: [d][token]
    __shared__ float se[DKC][TK];     // emb tile, transposed: [d][code]
    __shared__ float s_esq[KCODES];
    __shared__ float rv[16][TM];
    __shared__ int   ri[16][TM];
    __shared__ float bestv[TM];
    __shared__ int   besti[TM];
    __shared__ float red[256];
    __shared__ unsigned short cand[TM][MAXCAND];
    __shared__ int   ccnt[TM];

    const int tid  = threadIdx.x;
    const int tx   = tid & 15;    // token group: tokens tx*4 .. tx*4+3
    const int ty   = tid >> 4;    // code group:  codes  ty*8 .. ty*8+7
    const int tok0 = blockIdx.x * TM;

    for (int i = tid; i < KCODES; i += 256) s_esq[i] = g_esq[i];
    if (tid < TM) { bestv[tid] = 3.4e38f; ccnt[tid] = 0; }
    __syncthreads();

    for (int kc = 0; kc < KCODES; kc += TK) {
        unsigned long long acc[4][4];
        #pragma unroll
        for (int i = 0; i < 4; i++)
            #pragma unroll
            for (int j = 0; j < 4; j++) acc[i][j] = 0ull;

        for (int d0 = 0; d0 < DIM; d0 += DKC) {
            // --- load z tile: 64 tokens x 32 dims, 8 floats/thread ---
            {
                int tk = tid >> 2;            // token 0..63
                int dd = (tid & 3) * 8;       // dim offset 0/8/16/24
                const float* src = z + (size_t)(tok0 + tk) * DIM + d0 + dd;
                float4 a = *(const float4*)(src);
                float4 b = *(const float4*)(src + 4);
                sz[dd + 0][tk] = a.x; sz[dd + 1][tk] = a.y;
                sz[dd + 2][tk] = a.z; sz[dd + 3][tk] = a.w;
                sz[dd + 4][tk] = b.x; sz[dd + 5][tk] = b.y;
                sz[dd + 6][tk] = b.z; sz[dd + 7][tk] = b.w;
            }
            // --- load emb tile: 128 codes x 32 dims, 16 floats/thread ---
            {
                int code = tid >> 1;          // 0..127
                int dd = (tid & 1) * 16;
                const float* src = emb + (size_t)(kc + code) * DIM + d0 + dd;
                float4 a = *(const float4*)(src);
                float4 b = *(const float4*)(src + 4);
                float4 c = *(const float4*)(src + 8);
                float4 e = *(const float4*)(src + 12);
                se[dd +  0][code] = a.x; se[dd +  1][code] = a.y;
                se[dd +  2][code] = a.z; se[dd +  3][code] = a.w;
                se[dd +  4][code] = b.x; se[dd +  5][code] = b.y;
                se[dd +  6][code] = b.z; se[dd +  7][code] = b.w;
                se[dd +  8][code] = c.x; se[dd +  9][code] = c.y;
                se[dd + 10][code] = c.z; se[dd + 11][code] = c.w;
                se[dd + 12][code] = e.x; se[dd + 13][code] = e.y;
                se[dd + 14][code] = e.z; se[dd + 15][code] = e.w;
            }
            __syncthreads();

            #pragma unroll 8
            for (int d = 0; d < DKC; d++) {
                float4 zf = *(const float4*)&sz[d][tx * 4];
                double2 ea = *(const double2*)&se[d][ty * 8];
                double2 eb = *(const double2*)&se[d][ty * 8 + 4];
                unsigned long long ee[4];
                ee[0] = __double_as_longlong(ea.x);
                ee[1] = __double_as_longlong(ea.y);
                ee[2] = __double_as_longlong(eb.x);
                ee[3] = __double_as_longlong(eb.y);
                unsigned long long zz[4];
                zz[0] = pack2(zf.x); zz[1] = pack2(zf.y);
                zz[2] = pack2(zf.z); zz[3] = pack2(zf.w);
                #pragma unroll
                for (int i = 0; i < 4; i++)
                    #pragma unroll
                    for (int j = 0; j < 4; j++)
                        FMA_F32X2(acc[i][j], zz[i], ee[j], acc[i][j]);
            }
            __syncthreads();
        }

        // --- per-thread min over its 8 codes, for the approximate running min ---
        #pragma unroll
        for (int i = 0; i < 4; i++) {
            float lv = 3.4e38f; int li = 0;
            #pragma unroll
            for (int j = 0; j < 4; j++) {
                float lo, hi;
                unpack2(lo, hi, acc[i][j]);
                int c0 = kc + ty * 8 + 2 * j;
                float s0 = fmaf(-2.f, lo, s_esq[c0]);
                float s1 = fmaf(-2.f, hi, s_esq[c0 + 1]);
                if (s0 < lv) { lv = s0; li = c0; }
                if (s1 < lv) { lv = s1; li = c0 + 1; }
            }
            rv[ty][tx * 4 + i] = lv;
            ri[ty][tx * 4 + i] = li;
        }
        __syncthreads();
        if (tid < TM) {
            float bv = bestv[tid];
            #pragma unroll
            for (int j = 0; j < 16; j++) {
                float v = rv[j][tid];
                if (v < bv) bv = v;
            }
            bestv[tid] = bv;
        }
        __syncthreads();

        // --- candidate collection: anything within TAU of current min ---
        #pragma unroll
        for (int i = 0; i < 4; i++) {
            int tok = tx * 4 + i;
            float lim = bestv[tok] + TAU;
            #pragma unroll
            for (int j = 0; j < 4; j++) {
                float lo, hi;
                unpack2(lo, hi, acc[i][j]);
                int c0 = kc + ty * 8 + 2 * j;
                float s0 = fmaf(-2.f, lo, s_esq[c0]);
                float s1 = fmaf(-2.f, hi, s_esq[c0 + 1]);
                if (s0 <= lim) {
                    int p = atomicAdd(&ccnt[tok], 1);
                    if (p < MAXCAND) cand[tok][p] = (unsigned short)c0;
                }
                if (s1 <= lim) {
                    int p = atomicAdd(&ccnt[tok], 1);
                    if (p < MAXCAND) cand[tok][p] = (unsigned short)(c0 + 1);
                }
            }
        }
        __syncthreads();
    }

    // --- exact refine: XLA-emulated Z, cuBLAS-sequential dot ---
    if (tid < TM) {
        int token = tok0 + tid;
        const float* zr = z + (size_t)token * DIM;
        float Z32 = xla_rowsum_sq_192(zr);

        int cnt = ccnt[tid];
        float sBest = 3.4e38f;
        int iBest = 0x7fffffff;
        if (cnt <= MAXCAND) {
            for (int c = 0; c < cnt; c++) {
                int k = cand[tid][c];
                float s = exact_score(zr, emb + (size_t)k * DIM, Z32, s_esq[k]);
                if (s < sBest || (s == sBest && k < iBest)) { sBest = s; iBest = k; }
            }
        } else {
            for (int k = 0; k < KCODES; k++) {
                float s = exact_score(zr, emb + (size_t)k * DIM, Z32, s_esq[k]);
                if (s < sBest || (s == sBest && k < iBest)) { sBest = s; iBest = k; }
            }
        }
        besti[tid] = iBest;
    }
    __syncthreads();

    // --- epilogue: z_q_out = fl(z + fl(z_q - z)) (straight-through bits),
    //     idx output, loss partial on raw (z_q - z) ---
    float lsum = 0.f;
    const int NF4 = TM * (DIM / 4);   // 6144 float4s
    for (int i = tid; i < NF4; i += 256) {
        int t  = i / (DIM / 4);
        int d4 = i % (DIM / 4);
        int token = tok0 + t;
        int idx = besti[t];
        float4 e  = *(const float4*)(emb + (size_t)idx * DIM + d4 * 4);
        float4 zv = *(const float4*)(z + (size_t)token * DIM + d4 * 4);
        float dx = __fsub_rn(e.x, zv.x);
        float dy = __fsub_rn(e.y, zv.y);
        float dz = __fsub_rn(e.z, zv.z);
        float dw = __fsub_rn(e.w, zv.w);
        lsum += dx * dx + dy * dy + dz * dz + dw * dw;
        float4 o;
        o.x = __fadd_rn(zv.x, dx);
        o.y = __fadd_rn(zv.y, dy);
        o.z = __fadd_rn(zv.z, dz);
        o.w = __fadd_rn(zv.w, dw);
        *(float4*)(out + (size_t)token * DIM + d4 * 4) = o;
    }
    if (tid < TM)
        out[(size_t)N_TOK * DIM + tok0 + tid] = (float)besti[tid];

    red[tid] = lsum;
    __syncthreads();
    #pragma unroll
    for (int s = 128; s > 0; s >>= 1) {
        if (tid < s) red[tid] += red[tid + s];
        __syncthreads();
    }
    if (tid == 0) g_part[blockIdx.x] = red[0];
}

// ============================================================
// Kernel 3: deterministic loss finalize
// ============================================================
__global__ void vq_finalize_kernel(float* __restrict__ out) {
    __shared__ float red[512];
    int tid = threadIdx.x;
    float s = 0.f;
    for (int i = tid; i < NBLOCKS; i += 512) s += g_part[i];
    red[tid] = s;
    __syncthreads();
    #pragma unroll
    for (int o = 256; o > 0; o >>= 1) {
        if (tid < o) red[tid] += red[tid + o];
        __syncthreads();
    }
    if (tid == 0) {
        float mean = red[0] / (float)((size_t)N_TOK * DIM);
        out[(size_t)N_TOK * DIM + N_TOK] = (1.0f + BETA) * mean;
    }
}

// ============================================================
extern "C" void kernel_launch(void* const* d_in, const int* in_sizes, int n_in,
                              void* d_out, int out_size) {
    const float* z   = (const float*)d_in[0];
    const float* emb = (const float*)d_in[1];
    float* out = (float*)d_out;

    vq_esq_kernel<<<2, 256>>>(emb);
    vq_main_kernel<<<NBLOCKS, 256>>>(z, emb, out);
    vq_finalize_kernel<<<1, 512>>>(out);
}

// round 8
// speedup vs baseline: 1.0409x; 1.0409x over previous
#include <cuda_runtime.h>
#include <cuda_bf16.h>
#include <cstdint>

// Problem constants
#define N_TOK   262144
#define DIM     384
#define KCODES  512
#define BETA    0.25f

#define TOK_PB  128                    // tokens per block
#define NBLOCKS (N_TOK / TOK_PB)       // 2048
#define CODES_PC 64                    // codes per chunk
#define NCHUNK  (KCODES / CODES_PC)    // 8
#define TAU     0.06f                  // bf16 candidate margin
#define MAXCAND 16
#define ZROWB   784                    // padded smem row: 384*2 + 16 bytes

__device__ float g_esq[KCODES];
__device__ float g_part[NBLOCKS];
__device__ __nv_bfloat16 g_zbf[(size_t)N_TOK * DIM];
__device__ __nv_bfloat16 g_ebf[(size_t)KCODES * DIM];

// ---------------- PTX helpers (base sm_103 ISA only) ----------------
__device__ __forceinline__ uint32_t smem_u32(const void* p) {
    uint32_t a;
    asm("{ .reg .u64 t; cvta.to.shared.u64 t, %1; cvt.u32.u64 %0, t; }" : "=r"(a) : "l"(p));
    return a;
}

#define LDSM_X4(r0, r1, r2, r3, a) \
    asm volatile("ldmatrix.sync.aligned.m8n8.x4.shared.b16 {%0,%1,%2,%3}, [%4];" \
                 : "=r"(r0), "=r"(r1), "=r"(r2), "=r"(r3) : "r"(a))

#define MMA16816(d, a0, a1, a2, a3, b0, b1) \
    asm volatile("mma.sync.aligned.m16n8k16.row.col.f32.bf16.bf16.f32 " \
                 "{%0,%1,%2,%3}, {%4,%5,%6,%7}, {%8,%9}, {%0,%1,%2,%3};" \
                 : "+f"((d)[0]), "+f"((d)[1]), "+f"((d)[2]), "+f"((d)[3]) \
                 : "r"(a0), "r"(a1), "r"(a2), "r"(a3), "r"(b0), "r"(b1))

// ============================================================
// Exact-semantics primitives (DO NOT CHANGE — verified in R6)
// ============================================================
__device__ float xla_rowsum_sq_192(const float* __restrict__ x) {
    float W[6];
    #pragma unroll
    for (int w = 0; w < 6; w++) {
        float P[32];
        #pragma unroll
        for (int t = 0; t < 32; t++) {
            int b = (w * 32 + t) * 2;
            float p0 = __fmul_rn(x[b], x[b]);
            float p1 = __fmul_rn(x[b + 1], x[b + 1]);
            P[t] = __fadd_rn(p0, p1);
        }
        #pragma unroll
        for (int off = 16; off >= 1; off >>= 1) {
            #pragma unroll
            for (int t = 0; t < 16; t++)
                if (t < off) P[t] = __fadd_rn(P[t], P[t + off]);
        }
        W[w] = P[0];
    }
    float l0 = __fadd_rn(__fadd_rn(W[0], W[4]), W[2]);
    float l1 = __fadd_rn(__fadd_rn(W[1], W[5]), W[3]);
    return __fadd_rn(l0, l1);
}

__device__ __forceinline__ float exact_score(const float* __restrict__ zr,
                                             const float* __restrict__ er,
                                             float Z32, float esq32) {
    float acc = 0.f;
    #pragma unroll 4
    for (int d = 0; d < DIM; d++)
        acc = __fmaf_rn(zr[d], er[d], acc);
    float v1 = __fadd_rn(Z32, __fmul_rn(-2.f, acc));
    return __fadd_rn(v1, esq32);
}

// ============================================================
// Kernel 1: e_sq[k] (XLA row-reduce emulation — verified)
// ============================================================
__global__ void vq_esq_kernel(const float* __restrict__ emb) {
    int k = blockIdx.x * blockDim.x + threadIdx.x;
    if (k < KCODES)
        g_esq[k] = xla_rowsum_sq_192(emb + (size_t)k * DIM);
}

// ============================================================
// Kernel 2: fp32 -> bf16 conversion of z and emb
// ============================================================
__global__ void vq_cvt_kernel(const float* __restrict__ z,
                              const float* __restrict__ emb) {
    size_t i = (size_t)blockIdx.x * blockDim.x + threadIdx.x;
    size_t stride = (size_t)gridDim.x * blockDim.x;
    const size_t nz = (size_t)N_TOK * DIM / 2;
    for (size_t p = i; p < nz; p += stride) {
        float2 v = ((const float2*)z)[p];
        ((__nv_bfloat162*)g_zbf)[p] = __float22bfloat162_rn(v);
    }
    const size_t ne = (size_t)KCODES * DIM / 2;
    for (size_t p = i; p < ne; p += stride) {
        float2 v = ((const float2*)emb)[p];
        ((__nv_bfloat162*)g_ebf)[p] = __float22bfloat162_rn(v);
    }
}

// ============================================================
// Kernel 3: main — bf16 mma.sync fast pass + exact refine
// ============================================================
// dynamic smem layout (bytes)
#define SM_ESQ     0                        // 512*4   = 2048
#define SM_Z       2048                     // 128*784 = 100352
#define SM_E       102400                   // 64*784  = 50176
#define SM_CAND    152576                   // 128*16*2 = 4096
#define SM_CCNT    156672                   // 128*4 = 512
#define SM_BESTI   157184                   // 128*4 = 512
#define SM_RED     157696                   // 256*4 = 1024
#define SMEM_TOTAL 158720

__global__ __launch_bounds__(256, 1)
void vq_main_kernel(const float* __restrict__ z,
                    const float* __restrict__ emb,
                    float* __restrict__ out) {
    extern __shared__ char smem[];
    const uint32_t smb = smem_u32(smem);
    const int tid = threadIdx.x;
    const int w   = tid >> 5;          // warp = token group (16 tokens)
    const int lane = tid & 31;
    const int tok0 = blockIdx.x * TOK_PB;

    float* s_esq = (float*)(smem + SM_ESQ);
    unsigned short* s_cand = (unsigned short*)(smem + SM_CAND);
    int* s_ccnt  = (int*)(smem + SM_CCNT);
    int* s_besti = (int*)(smem + SM_BESTI);
    float* s_red = (float*)(smem + SM_RED);

    for (int i = tid; i < KCODES; i += 256) s_esq[i] = g_esq[i];
    if (tid < TOK_PB) s_ccnt[tid] = 0;

    // ---- load z tile: 128 rows x 384 bf16, 784B padded rows ----
    #pragma unroll
    for (int it = 0; it < 24; it++) {
        int idx = tid + it * 256;          // 0..6143
        int row = idx / 48, c = idx % 48;
        *(uint4*)(smem + SM_Z + row * ZROWB + c * 16) =
            *(const uint4*)(g_zbf + (size_t)(tok0 + row) * DIM + c * 8);
    }
    __syncthreads();

    // ldmatrix lane addressing
    const int lr = lane & 7;
    const int g4 = lane >> 3;
    // A (16x16): r0 rows0-7 k0 | r1 rows8-15 k0 | r2 rows0-7 k8 | r3 rows8-15 k8
    const uint32_t aAddr0 = smb + SM_Z
        + (uint32_t)((w * 16 + (g4 & 1) * 8 + lr) * ZROWB + ((g4 >> 1) * 8) * 2);
    // B (two n8k16 tiles per x4): r0/r1 tile rows0-7 (k0,k8) | r2/r3 rows8-15
    const uint32_t bAddr0 = smb + SM_E
        + (uint32_t)(((g4 >> 1) * 8 + lr) * ZROWB + ((g4 & 1) * 8) * 2);

    const int g  = lane >> 2;          // 0..7: row within warp tile
    const int cq = lane & 3;           // col pair selector
    const int tokA = w * 16 + g;       // local token ids this thread scores
    const int tokB = tokA + 8;

    float bv0 = 3.4e38f, bv1 = 3.4e38f;   // running minima (registers)

    for (int ch = 0; ch < NCHUNK; ch++) {
        const int cc0 = ch * CODES_PC;
        // ---- load emb chunk: 64 code rows x 384 bf16 ----
        #pragma unroll
        for (int it = 0; it < 12; it++) {
            int idx = tid + it * 256;      // 0..3071
            int row = idx / 48, c = idx % 48;
            *(uint4*)(smem + SM_E + row * ZROWB + c * 16) =
                *(const uint4*)(g_ebf + (size_t)(cc0 + row) * DIM + c * 8);
        }
        __syncthreads();

        float acc[8][4];
        #pragma unroll
        for (int nt = 0; nt < 8; nt++)
            #pragma unroll
            for (int v = 0; v < 4; v++) acc[nt][v] = 0.f;

        #pragma unroll 4
        for (int ks = 0; ks < DIM / 16; ks++) {
            uint32_t a0, a1, a2, a3;
            LDSM_X4(a0, a1, a2, a3, aAddr0 + ks * 32);
            #pragma unroll
            for (int i = 0; i < 4; i++) {
                uint32_t b0, b1, b2, b3;
                LDSM_X4(b0, b1, b2, b3, bAddr0 + i * (16 * ZROWB) + ks * 32);
                MMA16816(acc[2 * i],     a0, a1, a2, a3, b0, b1);
                MMA16816(acc[2 * i + 1], a0, a1, a2, a3, b2, b3);
            }
        }

        // ---- per-chunk min (rows tokA, tokB) ----
        float m0 = 3.4e38f, m1 = 3.4e38f;
        #pragma unroll
        for (int nt = 0; nt < 8; nt++) {
            int colb = cc0 + nt * 8 + cq * 2;
            float s00 = __fmaf_rn(-2.f, acc[nt][0], s_esq[colb]);
            float s01 = __fmaf_rn(-2.f, acc[nt][1], s_esq[colb + 1]);
            float s10 = __fmaf_rn(-2.f, acc[nt][2], s_esq[colb]);
            float s11 = __fmaf_rn(-2.f, acc[nt][3], s_esq[colb + 1]);
            m0 = fminf(m0, fminf(s00, s01));
            m1 = fminf(m1, fminf(s10, s11));
        }
        m0 = fminf(m0, __shfl_xor_sync(0xffffffffu, m0, 1));
        m0 = fminf(m0, __shfl_xor_sync(0xffffffffu, m0, 2));
        m1 = fminf(m1, __shfl_xor_sync(0xffffffffu, m1, 1));
        m1 = fminf(m1, __shfl_xor_sync(0xffffffffu, m1, 2));
        bv0 = fminf(bv0, m0);
        bv1 = fminf(bv1, m1);
        const float lim0 = bv0 + TAU, lim1 = bv1 + TAU;

        // ---- candidate collection vs running min (superset-safe) ----
        #pragma unroll
        for (int nt = 0; nt < 8; nt++) {
            int colb = cc0 + nt * 8 + cq * 2;
            #pragma unroll
            for (int v = 0; v < 4; v++) {
                int col = colb + (v & 1);
                float s = __fmaf_rn(-2.f, acc[nt][v], s_esq[col]);
                int tok = (v < 2) ? tokA : tokB;
                float lim = (v < 2) ? lim0 : lim1;
                if (s <= lim) {
                    int p = atomicAdd(&s_ccnt[tok], 1);
                    if (p < MAXCAND) s_cand[tok * MAXCAND + p] = (unsigned short)col;
                }
            }
        }
        __syncthreads();   // before emb tile overwrite
    }

    // ---- exact refine (verified R6 semantics — unchanged) ----
    if (tid < TOK_PB) {
        int token = tok0 + tid;
        const float* zr = z + (size_t)token * DIM;
        float Z32 = xla_rowsum_sq_192(zr);

        int cnt = s_ccnt[tid];
        float sBest = 3.4e38f;
        int iBest = 0x7fffffff;
        if (cnt <= MAXCAND) {
            for (int ci = 0; ci < cnt; ci++) {
                int k = s_cand[tid * MAXCAND + ci];
                float s = exact_score(zr, emb + (size_t)k * DIM, Z32, s_esq[k]);
                if (s < sBest || (s == sBest && k < iBest)) { sBest = s; iBest = k; }
            }
        } else {
            for (int k = 0; k < KCODES; k++) {
                float s = exact_score(zr, emb + (size_t)k * DIM, Z32, s_esq[k]);
                if (s < sBest || (s == sBest && k < iBest)) { sBest = s; iBest = k; }
            }
        }
        s_besti[tid] = iBest;
    }
    __syncthreads();

    // ---- epilogue: z_q_out = fl(z + fl(z_q - z)), idx, loss partial ----
    float lsum = 0.f;
    const int NF4 = TOK_PB * (DIM / 4);   // 12288
    for (int i = tid; i < NF4; i += 256) {
        int t  = i / (DIM / 4);
        int d4 = i % (DIM / 4);
        int token = tok0 + t;
        int idx = s_besti[t];
        float4 e  = *(const float4*)(emb + (size_t)idx * DIM + d4 * 4);
        float4 zv = *(const float4*)(z + (size_t)token * DIM + d4 * 4);
        float dx = __fsub_rn(e.x, zv.x);
        float dy = __fsub_rn(e.y, zv.y);
        float dz = __fsub_rn(e.z, zv.z);
        float dw = __fsub_rn(e.w, zv.w);
        lsum += dx * dx + dy * dy + dz * dz + dw * dw;
        float4 o;
        o.x = __fadd_rn(zv.x, dx);
        o.y = __fadd_rn(zv.y, dy);
        o.z = __fadd_rn(zv.z, dz);
        o.w = __fadd_rn(zv.w, dw);
        *(float4*)(out + (size_t)token * DIM + d4 * 4) = o;
    }
    if (tid < TOK_PB)
        out[(size_t)N_TOK * DIM + tok0 + tid] = (float)s_besti[tid];

    s_red[tid] = lsum;
    __syncthreads();
    #pragma unroll
    for (int s = 128; s > 0; s >>= 1) {
        if (tid < s) s_red[tid] += s_red[tid + s];
        __syncthreads();
    }
    if (tid == 0) g_part[blockIdx.x] = s_red[0];
}

// ============================================================
// Kernel 4: deterministic loss finalize
// ============================================================
__global__ void vq_finalize_kernel(float* __restrict__ out) {
    __shared__ float red[512];
    int tid = threadIdx.x;
    float s = 0.f;
    for (int i = tid; i < NBLOCKS; i += 512) s += g_part[i];
    red[tid] = s;
    __syncthreads();
    #pragma unroll
    for (int o = 256; o > 0; o >>= 1) {
        if (tid < o) red[tid] += red[tid + o];
        __syncthreads();
    }
    if (tid == 0) {
        float mean = red[0] / (float)((size_t)N_TOK * DIM);
        out[(size_t)N_TOK * DIM + N_TOK] = (1.0f + BETA) * mean;
    }
}

// ============================================================
extern "C" void kernel_launch(void* const* d_in, const int* in_sizes, int n_in,
                              void* d_out, int out_size) {
    const float* z   = (const float*)d_in[0];
    const float* emb = (const float*)d_in[1];
    float* out = (float*)d_out;

    cudaFuncSetAttribute(vq_main_kernel,
                         cudaFuncAttributeMaxDynamicSharedMemorySize, SMEM_TOTAL);

    vq_cvt_kernel<<<2048, 256>>>(z, emb);
    vq_esq_kernel<<<2, 256>>>(emb);
    vq_main_kernel<<<NBLOCKS, 256, SMEM_TOTAL>>>(z, emb, out);
    vq_finalize_kernel<<<1, 512>>>(out);
}

// round 9
// speedup vs baseline: 1.4657x; 1.4081x over previous
#include <cuda_runtime.h>
#include <cuda_bf16.h>
#include <cstdint>

// Problem constants
#define N_TOK   262144
#define DIM     384
#define KCODES  512
#define BETA    0.25f

#define TOK_PB  128                    // tokens per block
#define NBLOCKS (N_TOK / TOK_PB)       // 2048
#define CODES_PC 64                    // codes per chunk
#define NCHUNK  (KCODES / CODES_PC)    // 8
#define TAU     0.06f                  // bf16 candidate margin
#define MAXCAND 16
#define ZROWB   784                    // padded bf16 smem row: 384*2 + 16 bytes

__device__ float g_esq[KCODES];
__device__ float g_part[NBLOCKS];
__device__ __nv_bfloat16 g_zbf[(size_t)N_TOK * DIM];
__device__ __nv_bfloat16 g_ebf[(size_t)KCODES * DIM];
__device__ int g_ccnt[N_TOK];
__device__ unsigned short g_cand[(size_t)N_TOK * MAXCAND];

// ---------------- PTX helpers (base sm_103 ISA only) ----------------
__device__ __forceinline__ uint32_t smem_u32(const void* p) {
    uint32_t a;
    asm("{ .reg .u64 t; cvta.to.shared.u64 t, %1; cvt.u32.u64 %0, t; }" : "=r"(a) : "l"(p));
    return a;
}

#define LDSM_X4(r0, r1, r2, r3, a) \
    asm volatile("ldmatrix.sync.aligned.m8n8.x4.shared.b16 {%0,%1,%2,%3}, [%4];" \
                 : "=r"(r0), "=r"(r1), "=r"(r2), "=r"(r3) : "r"(a))

#define MMA16816(d, a0, a1, a2, a3, b0, b1) \
    asm volatile("mma.sync.aligned.m16n8k16.row.col.f32.bf16.bf16.f32 " \
                 "{%0,%1,%2,%3}, {%4,%5,%6,%7}, {%8,%9}, {%0,%1,%2,%3};" \
                 : "+f"((d)[0]), "+f"((d)[1]), "+f"((d)[2]), "+f"((d)[3]) \
                 : "r"(a0), "r"(a1), "r"(a2), "r"(a3), "r"(b0), "r"(b1))

#define CP_ASYNC16(dst, src) \
    asm volatile("cp.async.cg.shared.global [%0], [%1], 16;" \
                 :: "r"((uint32_t)(dst)), "l"(src) : "memory")
#define CP_COMMIT() asm volatile("cp.async.commit_group;" ::: "memory")
#define CP_WAIT1()  asm volatile("cp.async.wait_group 1;" ::: "memory")
#define CP_WAIT0()  asm volatile("cp.async.wait_group 0;" ::: "memory")

// ============================================================
// Exact-semantics primitives (DO NOT CHANGE — verified in R6/R8)
// ============================================================
__device__ float xla_rowsum_sq_192(const float* __restrict__ x) {
    float W[6];
    #pragma unroll
    for (int w = 0; w < 6; w++) {
        float P[32];
        #pragma unroll
        for (int t = 0; t < 32; t++) {
            int b = (w * 32 + t) * 2;
            float p0 = __fmul_rn(x[b], x[b]);
            float p1 = __fmul_rn(x[b + 1], x[b + 1]);
            P[t] = __fadd_rn(p0, p1);
        }
        #pragma unroll
        for (int off = 16; off >= 1; off >>= 1) {
            #pragma unroll
            for (int t = 0; t < 16; t++)
                if (t < off) P[t] = __fadd_rn(P[t], P[t + off]);
        }
        W[w] = P[0];
    }
    float l0 = __fadd_rn(__fadd_rn(W[0], W[4]), W[2]);
    float l1 = __fadd_rn(__fadd_rn(W[1], W[5]), W[3]);
    return __fadd_rn(l0, l1);
}

__device__ __forceinline__ float exact_score(const float* __restrict__ zr,
                                             const float* __restrict__ er,
                                             float Z32, float esq32) {
    float acc = 0.f;
    #pragma unroll 4
    for (int d = 0; d < DIM; d++)
        acc = __fmaf_rn(zr[d], er[d], acc);
    float v1 = __fadd_rn(Z32, __fmul_rn(-2.f, acc));
    return __fadd_rn(v1, esq32);
}

// ============================================================
// Kernel 1: e_sq[k] (verified)
// ============================================================
__global__ void vq_esq_kernel(const float* __restrict__ emb) {
    int k = blockIdx.x * blockDim.x + threadIdx.x;
    if (k < KCODES)
        g_esq[k] = xla_rowsum_sq_192(emb + (size_t)k * DIM);
}

// ============================================================
// Kernel 2: fp32 -> bf16 conversion + candidate-count reset
// ============================================================
__global__ void vq_cvt_kernel(const float* __restrict__ z,
                              const float* __restrict__ emb) {
    size_t i = (size_t)blockIdx.x * blockDim.x + threadIdx.x;
    size_t stride = (size_t)gridDim.x * blockDim.x;
    const size_t nz = (size_t)N_TOK * DIM / 2;
    for (size_t p = i; p < nz; p += stride) {
        float2 v = ((const float2*)z)[p];
        ((__nv_bfloat162*)g_zbf)[p] = __float22bfloat162_rn(v);
    }
    const size_t ne = (size_t)KCODES * DIM / 2;
    for (size_t p = i; p < ne; p += stride) {
        float2 v = ((const float2*)emb)[p];
        ((__nv_bfloat162*)g_ebf)[p] = __float22bfloat162_rn(v);
    }
    for (size_t p = i; p < N_TOK; p += stride) g_ccnt[p] = 0;
}

// ============================================================
// Kernel 3: fast pass — bf16 mma.sync, double-buffered emb via cp.async
// ============================================================
// smem layout (bytes)
#define FP_ESQ   0                        // 2048
#define FP_Z     2048                     // 128*784 = 100352
#define FP_E0    102400                   // 64*784  = 50176
#define FP_E1    152576                   // 50176
#define FP_TOTAL 202752

__global__ __launch_bounds__(256, 1)
void vq_fastpass_kernel() {
    extern __shared__ char smem[];
    const uint32_t smb = smem_u32(smem);
    const int tid = threadIdx.x;
    const int w   = tid >> 5;
    const int lane = tid & 31;
    const int tok0 = blockIdx.x * TOK_PB;

    float* s_esq = (float*)(smem + FP_ESQ);
    for (int i = tid; i < KCODES; i += 256) s_esq[i] = g_esq[i];

    // z tile (async) + first emb chunk (async), one group
    #pragma unroll
    for (int it = 0; it < 24; it++) {
        int idx = tid + it * 256;
        int row = idx / 48, c = idx % 48;
        CP_ASYNC16(smb + FP_Z + row * ZROWB + c * 16,
                   g_zbf + (size_t)(tok0 + row) * DIM + c * 8);
    }
    #pragma unroll
    for (int it = 0; it < 12; it++) {
        int idx = tid + it * 256;
        int row = idx / 48, c = idx % 48;
        CP_ASYNC16(smb + FP_E0 + row * ZROWB + c * 16,
                   g_ebf + (size_t)row * DIM + c * 8);
    }
    CP_COMMIT();

    // ldmatrix lane addressing
    const int lr = lane & 7;
    const int g4 = lane >> 3;
    const uint32_t aAddr0 = smb + FP_Z
        + (uint32_t)((w * 16 + (g4 & 1) * 8 + lr) * ZROWB + ((g4 >> 1) * 8) * 2);
    const uint32_t bOff = (uint32_t)(((g4 >> 1) * 8 + lr) * ZROWB + ((g4 & 1) * 8) * 2);
    const uint32_t bBase[2] = { smb + FP_E0 + bOff, smb + FP_E1 + bOff };

    const int g  = lane >> 2;
    const int cq = lane & 3;
    const int tokA = tok0 + w * 16 + g;     // global token ids
    const int tokB = tokA + 8;

    float bv0 = 3.4e38f, bv1 = 3.4e38f;

    for (int ch = 0; ch < NCHUNK; ch++) {
        if (ch + 1 < NCHUNK) {
            const int cc1 = (ch + 1) * CODES_PC;
            const uint32_t ebuf = (ch + 1) & 1 ? (smb + FP_E1) : (smb + FP_E0);
            #pragma unroll
            for (int it = 0; it < 12; it++) {
                int idx = tid + it * 256;
                int row = idx / 48, c = idx % 48;
                CP_ASYNC16(ebuf + row * ZROWB + c * 16,
                           g_ebf + (size_t)(cc1 + row) * DIM + c * 8);
            }
            CP_COMMIT();
            CP_WAIT1();
        } else {
            CP_WAIT0();
        }
        __syncthreads();

        const int cc0 = ch * CODES_PC;
        const uint32_t bAddr0 = bBase[ch & 1];

        float acc[8][4];
        #pragma unroll
        for (int nt = 0; nt < 8; nt++)
            #pragma unroll
            for (int v = 0; v < 4; v++) acc[nt][v] = 0.f;

        #pragma unroll 4
        for (int ks = 0; ks < DIM / 16; ks++) {
            uint32_t a0, a1, a2, a3;
            LDSM_X4(a0, a1, a2, a3, aAddr0 + ks * 32);
            #pragma unroll
            for (int i = 0; i < 4; i++) {
                uint32_t b0, b1, b2, b3;
                LDSM_X4(b0, b1, b2, b3, bAddr0 + i * (16 * ZROWB) + ks * 32);
                MMA16816(acc[2 * i],     a0, a1, a2, a3, b0, b1);
                MMA16816(acc[2 * i + 1], a0, a1, a2, a3, b2, b3);
            }
        }

        // per-chunk min across this token's quad
        float m0 = 3.4e38f, m1 = 3.4e38f;
        #pragma unroll
        for (int nt = 0; nt < 8; nt++) {
            int colb = cc0 + nt * 8 + cq * 2;
            float s00 = __fmaf_rn(-2.f, acc[nt][0], s_esq[colb]);
            float s01 = __fmaf_rn(-2.f, acc[nt][1], s_esq[colb + 1]);
            float s10 = __fmaf_rn(-2.f, acc[nt][2], s_esq[colb]);
            float s11 = __fmaf_rn(-2.f, acc[nt][3], s_esq[colb + 1]);
            m0 = fminf(m0, fminf(s00, s01));
            m1 = fminf(m1, fminf(s10, s11));
        }
        m0 = fminf(m0, __shfl_xor_sync(0xffffffffu, m0, 1));
        m0 = fminf(m0, __shfl_xor_sync(0xffffffffu, m0, 2));
        m1 = fminf(m1, __shfl_xor_sync(0xffffffffu, m1, 1));
        m1 = fminf(m1, __shfl_xor_sync(0xffffffffu, m1, 2));
        bv0 = fminf(bv0, m0);
        bv1 = fminf(bv1, m1);
        const float lim0 = bv0 + TAU, lim1 = bv1 + TAU;

        // candidate collection vs running min (superset-safe)
        #pragma unroll
        for (int nt = 0; nt < 8; nt++) {
            int colb = cc0 + nt * 8 + cq * 2;
            #pragma unroll
            for (int v = 0; v < 4; v++) {
                int col = colb + (v & 1);
                float s = __fmaf_rn(-2.f, acc[nt][v], s_esq[col]);
                int tok = (v < 2) ? tokA : tokB;
                float lim = (v < 2) ? lim0 : lim1;
                if (s <= lim) {
                    int p = atomicAdd(&g_ccnt[tok], 1);
                    if (p < MAXCAND) g_cand[(size_t)tok * MAXCAND + p] = (unsigned short)col;
                }
            }
        }
        __syncthreads();   // all reads of current emb buffer done before reuse
    }
}

// ============================================================
// Kernel 4: refine + epilogue (exact R6 semantics from smem-staged z)
// ============================================================
#define RF_ZROW  385                       // padded fp32 row (conflict-free LDS)
#define RF_Z     0                         // 128*385*4 = 197120
#define RF_ESQ   197120                    // 2048
#define RF_BESTI 199168                    // 512
#define RF_RED   199680                    // 1024
#define RF_TOTAL 200704

__global__ __launch_bounds__(256, 1)
void vq_refine_kernel(const float* __restrict__ z,
                      const float* __restrict__ emb,
                      float* __restrict__ out) {
    extern __shared__ char smem[];
    float* s_z = (float*)(smem + RF_Z);
    float* s_esq = (float*)(smem + RF_ESQ);
    int* s_besti = (int*)(smem + RF_BESTI);
    float* s_red = (float*)(smem + RF_RED);
    const int tid = threadIdx.x;
    const int tok0 = blockIdx.x * TOK_PB;

    for (int i = tid; i < KCODES; i += 256) s_esq[i] = g_esq[i];

    // stage z tile coalesced: 128 rows x 384 floats (padded rows of 385)
    #pragma unroll
    for (int it = 0; it < 48; it++) {
        int idx = tid + it * 256;          // 0..12287
        int row = idx / 96, c = idx % 96;
        float4 v = *(const float4*)(z + (size_t)(tok0 + row) * DIM + c * 4);
        float* dst = s_z + row * RF_ZROW + c * 4;
        dst[0] = v.x; dst[1] = v.y; dst[2] = v.z; dst[3] = v.w;
    }
    __syncthreads();

    // exact refine (verified semantics — values/order identical, now from smem)
    if (tid < TOK_PB) {
        int token = tok0 + tid;
        const float* zr = s_z + tid * RF_ZROW;
        float Z32 = xla_rowsum_sq_192(zr);

        int cnt = g_ccnt[token];
        float sBest = 3.4e38f;
        int iBest = 0x7fffffff;
        if (cnt <= MAXCAND) {
            for (int ci = 0; ci < cnt; ci++) {
                int k = g_cand[(size_t)token * MAXCAND + ci];
                float s = exact_score(zr, emb + (size_t)k * DIM, Z32, s_esq[k]);
                if (s < sBest || (s == sBest && k < iBest)) { sBest = s; iBest = k; }
            }
        } else {
            for (int k = 0; k < KCODES; k++) {
                float s = exact_score(zr, emb + (size_t)k * DIM, Z32, s_esq[k]);
                if (s < sBest || (s == sBest && k < iBest)) { sBest = s; iBest = k; }
            }
        }
        s_besti[tid] = iBest;
    }
    __syncthreads();

    // epilogue: z_q_out = fl(z + fl(z_q - z)), idx, loss partial
    float lsum = 0.f;
    const int NF4 = TOK_PB * (DIM / 4);   // 12288
    for (int i = tid; i < NF4; i += 256) {
        int t  = i / (DIM / 4);
        int d4 = i % (DIM / 4);
        int token = tok0 + t;
        int idx = s_besti[t];
        float4 e = *(const float4*)(emb + (size_t)idx * DIM + d4 * 4);
        const float* zp = s_z + t * RF_ZROW + d4 * 4;
        float dx = __fsub_rn(e.x, zp[0]);
        float dy = __fsub_rn(e.y, zp[1]);
        float dz = __fsub_rn(e.z, zp[2]);
        float dw = __fsub_rn(e.w, zp[3]);
        lsum += dx * dx + dy * dy + dz * dz + dw * dw;
        float4 o;
        o.x = __fadd_rn(zp[0], dx);
        o.y = __fadd_rn(zp[1], dy);
        o.z = __fadd_rn(zp[2], dz);
        o.w = __fadd_rn(zp[3], dw);
        *(float4*)(out + (size_t)token * DIM + d4 * 4) = o;
    }
    if (tid < TOK_PB)
        out[(size_t)N_TOK * DIM + tok0 + tid] = (float)s_besti[tid];

    s_red[tid] = lsum;
    __syncthreads();
    #pragma unroll
    for (int s = 128; s > 0; s >>= 1) {
        if (tid < s) s_red[tid] += s_red[tid + s];
        __syncthreads();
    }
    if (tid == 0) g_part[blockIdx.x] = s_red[0];
}

// ============================================================
// Kernel 5: deterministic loss finalize
// ============================================================
__global__ void vq_finalize_kernel(float* __restrict__ out) {
    __shared__ float red[512];
    int tid = threadIdx.x;
    float s = 0.f;
    for (int i = tid; i < NBLOCKS; i += 512) s += g_part[i];
    red[tid] = s;
    __syncthreads();
    #pragma unroll
    for (int o = 256; o > 0; o >>= 1) {
        if (tid < o) red[tid] += red[tid + o];
        __syncthreads();
    }
    if (tid == 0) {
        float mean = red[0] / (float)((size_t)N_TOK * DIM);
        out[(size_t)N_TOK * DIM + N_TOK] = (1.0f + BETA) * mean;
    }
}

// ============================================================
extern "C" void kernel_launch(void* const* d_in, const int* in_sizes, int n_in,
                              void* d_out, int out_size) {
    const float* z   = (const float*)d_in[0];
    const float* emb = (const float*)d_in[1];
    float* out = (float*)d_out;

    cudaFuncSetAttribute(vq_fastpass_kernel,
                         cudaFuncAttributeMaxDynamicSharedMemorySize, FP_TOTAL);
    cudaFuncSetAttribute(vq_refine_kernel,
                         cudaFuncAttributeMaxDynamicSharedMemorySize, RF_TOTAL);

    vq_cvt_kernel<<<2048, 256>>>(z, emb);
    vq_esq_kernel<<<2, 256>>>(emb);
    vq_fastpass_kernel<<<NBLOCKS, 256, FP_TOTAL>>>();
    vq_refine_kernel<<<NBLOCKS, 256, RF_TOTAL>>>(z, emb, out);
    vq_finalize_kernel<<<1, 512>>>(out);
}